// round 1
// baseline (speedup 1.0000x reference)
#include <cuda_runtime.h>
#include <math.h>

#define BDIM 4
#define DIMZ 192
#define DIMY 192
#define DIMX 192
#define NTOT (BDIM*DIMZ*DIMY*DIMX)   // 28,311,552

#define C1f 1.0e-4f
#define C2f 9.0e-4f

struct Wts { float w[11]; };

// Scratch: 5 channels, two ping-pong buffers (allowed: __device__ globals).
__device__ float g_scrA[5ull * NTOT];
__device__ float g_scrB[5ull * NTOT];
__device__ double g_acc;

__global__ void k_zero() { g_acc = 0.0; }

// ---------------------------------------------------------------------------
// Pass 1: read gt/pred, build 5 channels on the fly, blur along x (contiguous).
// One smem row (zero-padded) per (b,z,y); block loops over 8 rows.
// ---------------------------------------------------------------------------
__global__ void __launch_bounds__(192) k_xblur(const float* __restrict__ gt,
                                               const float* __restrict__ pr,
                                               Wts W) {
    __shared__ float gs[DIMX + 10];
    __shared__ float ps[DIMX + 10];
    const int x = threadIdx.x;           // 0..191
    const int z = blockIdx.x;            // 0..191
    const int yg = blockIdx.y;           // 0..23
    const int b = blockIdx.z;            // 0..3

    for (int r = 0; r < 8; ++r) {
        const int y = yg * 8 + r;
        const size_t base = (((size_t)b * DIMZ + z) * DIMY + y) * DIMX;
        gs[x + 5] = gt[base + x];
        ps[x + 5] = pr[base + x];
        if (x < 5) {
            gs[x] = 0.f; ps[x] = 0.f;
            gs[x + DIMX + 5] = 0.f; ps[x + DIMX + 5] = 0.f;
        }
        __syncthreads();

        float s0 = 0.f, s1 = 0.f, s2 = 0.f, s3 = 0.f, s4 = 0.f;
#pragma unroll
        for (int k = 0; k < 11; ++k) {
            const float wk = W.w[k];
            const float gv = gs[x + k];
            const float pv = ps[x + k];
            const float tg = wk * gv;
            const float tp = wk * pv;
            s0 += tg;            // blur(gt)
            s1 += tp;            // blur(pred)
            s2 += tg * gv;       // blur(gt^2)
            s3 += tp * pv;       // blur(pred^2)
            s4 += tg * pv;       // blur(gt*pred)
        }
        const size_t idx = base + x;
        g_scrA[0ull * NTOT + idx] = s0;
        g_scrA[1ull * NTOT + idx] = s1;
        g_scrA[2ull * NTOT + idx] = s2;
        g_scrA[3ull * NTOT + idx] = s3;
        g_scrA[4ull * NTOT + idx] = s4;
        __syncthreads();
    }
}

// ---------------------------------------------------------------------------
// Pass 2: blur along y with a rolling 11-deep register window per channel.
// Each thread owns one (b,z,x) column segment of 48 y-outputs.
// Circular buffer: value with u-index stored at slot u%11 (all static after
// unroll-by-11). 1 LDG per output per channel, coalesced across tx.
// ---------------------------------------------------------------------------
__global__ void __launch_bounds__(128) k_yblur(Wts W) {
    const int tx = threadIdx.x;          // 0..31
    const int ty = threadIdx.y;          // 0..3
    const int x = blockIdx.x * 32 + tx;  // 0..191
    const int z = blockIdx.y;
    const int b = blockIdx.z;
    const int ystart = ty * 48;

    const size_t colbase = (((size_t)b * DIMZ + z) * DIMY) * DIMX + x; // +y*DIMX

    float win[5][11];
#pragma unroll
    for (int c = 0; c < 5; ++c)
#pragma unroll
        for (int s = 0; s < 11; ++s) win[c][s] = 0.f;

    // Prologue: u = 0..9 holds input yin = ystart-5+u (zeros below boundary).
#pragma unroll
    for (int u = 0; u < 10; ++u) {
        const int yin = ystart - 5 + u;
        if (yin >= 0) {
            const size_t off = colbase + (size_t)yin * DIMX;
#pragma unroll
            for (int c = 0; c < 5; ++c)
                win[c][u] = g_scrA[(size_t)c * NTOT + off];
        }
    }

    for (int jb = 0; jb < 48; jb += 11) {
#pragma unroll
        for (int i = 0; i < 11; ++i) {
            const int j = jb + i;
            if (j < 48) {
                // Load u = j+10 (input yin = ystart+j+5) into slot (i+10)%11.
                const int slot = (i + 10) % 11;
                const int yin = ystart + j + 5;
                const size_t off = colbase + (size_t)yin * DIMX;
#pragma unroll
                for (int c = 0; c < 5; ++c)
                    win[c][slot] = (yin < DIMY) ? g_scrA[(size_t)c * NTOT + off] : 0.f;

                float m0 = 0.f, m1 = 0.f, m2 = 0.f, m3 = 0.f, m4 = 0.f;
#pragma unroll
                for (int s = 0; s < 11; ++s) {
                    const int wi = ((s - i) % 11 + 11) % 11;   // static
                    const float wk = W.w[wi];
                    m0 += wk * win[0][s];
                    m1 += wk * win[1][s];
                    m2 += wk * win[2][s];
                    m3 += wk * win[3][s];
                    m4 += wk * win[4][s];
                }
                const int y = ystart + j;
                const size_t oidx = colbase + (size_t)y * DIMX;
                g_scrB[0ull * NTOT + oidx] = m0;
                g_scrB[1ull * NTOT + oidx] = m1;
                g_scrB[2ull * NTOT + oidx] = m2;
                g_scrB[3ull * NTOT + oidx] = m3;
                g_scrB[4ull * NTOT + oidx] = m4;
            }
        }
    }
}

// ---------------------------------------------------------------------------
// Pass 3: blur along z (rolling window), SSIM map, mean(1-ssim) reduction.
// Thread owns one (b,y,x) column over all 192 z. Block (192 threads over x),
// grid (Y, B).
// ---------------------------------------------------------------------------
__global__ void __launch_bounds__(192) k_zssim(Wts W) {
    const int x = threadIdx.x;
    const int y = blockIdx.x;
    const int b = blockIdx.y;

    const size_t colbase = (((size_t)b * DIMZ) * DIMY + y) * DIMX + x; // +z*DIMY*DIMX
    const size_t zstride = (size_t)DIMY * DIMX;

    float win[5][11];
#pragma unroll
    for (int c = 0; c < 5; ++c)
#pragma unroll
        for (int s = 0; s < 11; ++s) win[c][s] = 0.f;

    // Prologue: u=0..9 -> zin = u-5 (only zin>=0 exist)
#pragma unroll
    for (int u = 0; u < 10; ++u) {
        const int zin = u - 5;
        if (zin >= 0) {
            const size_t off = colbase + (size_t)zin * zstride;
#pragma unroll
            for (int c = 0; c < 5; ++c)
                win[c][u] = g_scrB[(size_t)c * NTOT + off];
        }
    }

    float acc = 0.f;
    for (int jb = 0; jb < 192; jb += 11) {
#pragma unroll
        for (int i = 0; i < 11; ++i) {
            const int j = jb + i;  // output z
            if (j < DIMZ) {
                const int slot = (i + 10) % 11;
                const int zin = j + 5;
                const size_t off = colbase + (size_t)zin * zstride;
#pragma unroll
                for (int c = 0; c < 5; ++c)
                    win[c][slot] = (zin < DIMZ) ? g_scrB[(size_t)c * NTOT + off] : 0.f;

                float m0 = 0.f, m1 = 0.f, m2 = 0.f, m3 = 0.f, m4 = 0.f;
#pragma unroll
                for (int s = 0; s < 11; ++s) {
                    const int wi = ((s - i) % 11 + 11) % 11;   // static
                    const float wk = W.w[wi];
                    m0 += wk * win[0][s];
                    m1 += wk * win[1][s];
                    m2 += wk * win[2][s];
                    m3 += wk * win[3][s];
                    m4 += wk * win[4][s];
                }
                // SSIM
                const float mux = m0, muy = m1;
                const float mux2 = mux * mux;
                const float muy2 = muy * muy;
                const float muxy = mux * muy;
                const float sx = m2 - mux2;
                const float sy = m3 - muy2;
                const float sxy = m4 - muxy;
                const float num = (2.f * muxy + C1f) * (2.f * sxy + C2f);
                const float den = (mux2 + muy2 + C1f) * (sx + sy + C2f);
                acc += 1.f - __fdividef(num, den);
            }
        }
    }

    // Block reduction -> double atomic
    __shared__ float red[6];
    float v = acc;
#pragma unroll
    for (int o = 16; o > 0; o >>= 1)
        v += __shfl_down_sync(0xffffffffu, v, o);
    const int wid = threadIdx.x >> 5;
    if ((threadIdx.x & 31) == 0) red[wid] = v;
    __syncthreads();
    if (threadIdx.x == 0) {
        float t = 0.f;
#pragma unroll
        for (int w = 0; w < 6; ++w) t += red[w];
        atomicAdd(&g_acc, (double)t);
    }
}

__global__ void k_final(float* __restrict__ out) {
    out[0] = (float)(g_acc * (1.0 / (double)NTOT));
}

// ---------------------------------------------------------------------------
extern "C" void kernel_launch(void* const* d_in, const int* in_sizes, int n_in,
                              void* d_out, int out_size) {
    const float* gt = (const float*)d_in[0];
    const float* pr = (const float*)d_in[1];
    float* out = (float*)d_out;

    // Gaussian weights: double precision, normalized, cast to float
    // (matches numpy float64 -> float32). The 1/(sqrt(2pi)sigma) cancels.
    Wts W;
    {
        double g[11], sum = 0.0;
        for (int i = 0; i < 11; ++i) {
            const double xx = (double)(i - 5);
            g[i] = exp(-(xx * xx) / (2.0 * 1.5 * 1.5));
            sum += g[i];
        }
        for (int i = 0; i < 11; ++i) W.w[i] = (float)(g[i] / sum);
    }

    k_zero<<<1, 1>>>();
    k_xblur<<<dim3(DIMZ, 24, BDIM), 192>>>(gt, pr, W);
    k_yblur<<<dim3(6, DIMZ, BDIM), dim3(32, 4)>>>(W);
    k_zssim<<<dim3(DIMY, BDIM), 192>>>(W);
    k_final<<<1, 1>>>(out);
}

// round 3
// speedup vs baseline: 1.3986x; 1.3986x over previous
#include <cuda_runtime.h>
#include <math.h>

#define BDIM 4
#define DIMZ 192
#define DIMY 192
#define DIMX 192
#define NTOT (BDIM*DIMZ*DIMY*DIMX)   // 28,311,552

#define C1f 1.0e-4f
#define C2f 9.0e-4f

struct Wts { float w[11]; };

// Scratch: 5 channels, xy-blurred. __device__ global (no mallocs).
__device__ float g_scrA[5ull * NTOT];
__device__ double g_acc;

__global__ void k_zero() { g_acc = 0.0; }

// ---------------------------------------------------------------------------
// Pass 1: fused channel-gen + x-blur + y-blur.
// Block = one (b,z) slice, 192 threads (one per x). Scans y with a single
// smem row buffer (stage -> sync -> consume -> sync) and a thread-private
// 5ch x 11 register ring for the y window. All load addresses clamped
// in-bounds; zero-padding applied by select after the load.
// ---------------------------------------------------------------------------
__global__ void __launch_bounds__(192) k_xyblur(const float* __restrict__ gt,
                                                const float* __restrict__ pr,
                                                Wts W) {
    __shared__ float sg[DIMX + 10];
    __shared__ float sp[DIMX + 10];
    const int x = threadIdx.x;           // 0..191
    const int z = blockIdx.x;            // 0..191
    const int b = blockIdx.y;            // 0..3

    const size_t slice = (((size_t)b * DIMZ + z) * DIMY) * DIMX;

    // Zero the constant halo once (covered by the first __syncthreads below).
    if (x < 5) {
        sg[x] = 0.f; sp[x] = 0.f;
        sg[DIMX + 5 + x] = 0.f; sp[DIMX + 5 + x] = 0.f;
    }

    float win[5][11];
#pragma unroll
    for (int c = 0; c < 5; ++c)
#pragma unroll
        for (int s = 0; s < 11; ++s) win[c][s] = 0.f;

    // Prologue: insert raw rows yin = 0..4 at ring slots yin+5 (5..9).
#pragma unroll
    for (int yin = 0; yin < 5; ++yin) {
        sg[x + 5] = gt[slice + (size_t)yin * DIMX + x];
        sp[x + 5] = pr[slice + (size_t)yin * DIMX + x];
        __syncthreads();
        float s0 = 0.f, s1 = 0.f, s2 = 0.f, s3 = 0.f, s4 = 0.f;
#pragma unroll
        for (int k = 0; k < 11; ++k) {
            const float wk = W.w[k];
            const float gv = sg[x + k];
            const float pv = sp[x + k];
            const float tg = wk * gv, tp = wk * pv;
            s0 += tg; s1 += tp; s2 += tg * gv; s3 += tp * pv; s4 += tg * pv;
        }
        const int slot = yin + 5;
        win[0][slot] = s0; win[1][slot] = s1; win[2][slot] = s2;
        win[3][slot] = s3; win[4][slot] = s4;
        __syncthreads();   // protect buffer reuse
    }

    for (int jb = 0; jb < DIMY; jb += 11) {
#pragma unroll
        for (int i = 0; i < 11; ++i) {
            const int y = jb + i;          // uniform across block
            if (y < DIMY) {
                const int yin = y + 5;     // row inserted this iteration
                // Clamped (always in-bounds) load; zero-select afterwards.
                const int yc = (yin < DIMY) ? yin : (DIMY - 1);
                float gv = gt[slice + (size_t)yc * DIMX + x];
                float pv = pr[slice + (size_t)yc * DIMX + x];
                if (yin >= DIMY) { gv = 0.f; pv = 0.f; }
                sg[x + 5] = gv;
                sp[x + 5] = pv;
                __syncthreads();

                // x-blur row yin -> ring slot (i+10)%11 (static per i).
                const int slot = (i + 10) % 11;
                {
                    float s0 = 0.f, s1 = 0.f, s2 = 0.f, s3 = 0.f, s4 = 0.f;
#pragma unroll
                    for (int k = 0; k < 11; ++k) {
                        const float wk = W.w[k];
                        const float g2 = sg[x + k];
                        const float p2 = sp[x + k];
                        const float tg = wk * g2, tp = wk * p2;
                        s0 += tg; s1 += tp; s2 += tg * g2; s3 += tp * p2; s4 += tg * p2;
                    }
                    win[0][slot] = s0; win[1][slot] = s1; win[2][slot] = s2;
                    win[3][slot] = s3; win[4][slot] = s4;
                }

                // y-blur for output y: tap t uses slot (i+t)%11 (static).
                float m0 = 0.f, m1 = 0.f, m2 = 0.f, m3 = 0.f, m4 = 0.f;
#pragma unroll
                for (int t = 0; t < 11; ++t) {
                    const int s = (i + t) % 11;
                    const float wk = W.w[t];
                    m0 += wk * win[0][s];
                    m1 += wk * win[1][s];
                    m2 += wk * win[2][s];
                    m3 += wk * win[3][s];
                    m4 += wk * win[4][s];
                }
                const size_t oidx = slice + (size_t)y * DIMX + x;
                g_scrA[0ull * NTOT + oidx] = m0;
                g_scrA[1ull * NTOT + oidx] = m1;
                g_scrA[2ull * NTOT + oidx] = m2;
                g_scrA[3ull * NTOT + oidx] = m3;
                g_scrA[4ull * NTOT + oidx] = m4;
                __syncthreads();   // protect buffer reuse next iteration
            }
        }
    }
}

// ---------------------------------------------------------------------------
// Pass 2: z-blur + SSIM + mean reduction (round-1 structure + 4 z-segments).
// All load addresses clamped in-bounds; zero-select after the load.
// ---------------------------------------------------------------------------
__global__ void __launch_bounds__(192) k_zssim(Wts W) {
    const int x = threadIdx.x;
    const int y = blockIdx.x;
    const int seg = blockIdx.y;          // 0..3
    const int b = blockIdx.z;
    const int zs = seg * 48;

    const size_t colbase = (((size_t)b * DIMZ) * DIMY + y) * DIMX + x;
    const size_t zstride = (size_t)DIMY * DIMX;

    float win[5][11];
#pragma unroll
    for (int c = 0; c < 5; ++c)
#pragma unroll
        for (int s = 0; s < 11; ++s) win[c][s] = 0.f;

    // Prologue: u = 0..9 -> zin = zs-5+u (clamp low end; high end <= 148).
#pragma unroll
    for (int u = 0; u < 10; ++u) {
        const int zin = zs - 5 + u;
        const int zc = (zin >= 0) ? zin : 0;
        const size_t off = colbase + (size_t)zc * zstride;
#pragma unroll
        for (int c = 0; c < 5; ++c) {
            const float v = g_scrA[(size_t)c * NTOT + off];
            win[c][u] = (zin >= 0) ? v : 0.f;
        }
    }

    float acc = 0.f;
    for (int jb = 0; jb < 48; jb += 11) {
#pragma unroll
        for (int i = 0; i < 11; ++i) {
            const int j = jb + i;
            if (j < 48) {
                // Insert u = j+10 (zin = zs+j+5) at slot (i+10)%11 (static).
                const int slot = (i + 10) % 11;
                const int zin = zs + j + 5;
                const int zc = (zin < DIMZ) ? zin : (DIMZ - 1);
                const size_t off = colbase + (size_t)zc * zstride;
#pragma unroll
                for (int c = 0; c < 5; ++c) {
                    const float v = g_scrA[(size_t)c * NTOT + off];
                    win[c][slot] = (zin < DIMZ) ? v : 0.f;
                }

                float m0 = 0.f, m1 = 0.f, m2 = 0.f, m3 = 0.f, m4 = 0.f;
#pragma unroll
                for (int t = 0; t < 11; ++t) {
                    const int s = (i + t) % 11;   // static
                    const float wk = W.w[t];
                    m0 += wk * win[0][s];
                    m1 += wk * win[1][s];
                    m2 += wk * win[2][s];
                    m3 += wk * win[3][s];
                    m4 += wk * win[4][s];
                }
                const float mux = m0, muy = m1;
                const float mux2 = mux * mux;
                const float muy2 = muy * muy;
                const float muxy = mux * muy;
                const float sx = m2 - mux2;
                const float sy = m3 - muy2;
                const float sxy = m4 - muxy;
                const float num = (2.f * muxy + C1f) * (2.f * sxy + C2f);
                const float den = (mux2 + muy2 + C1f) * (sx + sy + C2f);
                acc += 1.f - __fdividef(num, den);
            }
        }
    }

    // Block reduction -> double atomic
    __shared__ float red[6];
    float v = acc;
#pragma unroll
    for (int o = 16; o > 0; o >>= 1)
        v += __shfl_down_sync(0xffffffffu, v, o);
    const int wid = threadIdx.x >> 5;
    if ((threadIdx.x & 31) == 0) red[wid] = v;
    __syncthreads();
    if (threadIdx.x == 0) {
        float t = 0.f;
#pragma unroll
        for (int w = 0; w < 6; ++w) t += red[w];
        atomicAdd(&g_acc, (double)t);
    }
}

__global__ void k_final(float* __restrict__ out) {
    out[0] = (float)(g_acc * (1.0 / (double)NTOT));
}

// ---------------------------------------------------------------------------
extern "C" void kernel_launch(void* const* d_in, const int* in_sizes, int n_in,
                              void* d_out, int out_size) {
    const float* gt = (const float*)d_in[0];
    const float* pr = (const float*)d_in[1];
    float* out = (float*)d_out;

    Wts W;
    {
        double g[11], sum = 0.0;
        for (int i = 0; i < 11; ++i) {
            const double xx = (double)(i - 5);
            g[i] = exp(-(xx * xx) / (2.0 * 1.5 * 1.5));
            sum += g[i];
        }
        for (int i = 0; i < 11; ++i) W.w[i] = (float)(g[i] / sum);
    }

    k_zero<<<1, 1>>>();
    k_xyblur<<<dim3(DIMZ, BDIM), 192>>>(gt, pr, W);
    k_zssim<<<dim3(DIMY, 4, BDIM), 192>>>(W);
    k_final<<<1, 1>>>(out);
}

// round 4
// speedup vs baseline: 1.5832x; 1.1320x over previous
#include <cuda_runtime.h>
#include <math.h>

#define BDIM 4
#define DIMZ 192
#define DIMY 192
#define DIMX 192
#define NTOT (BDIM*DIMZ*DIMY*DIMX)   // 28,311,552
#define NPART (DIMY * 4 * BDIM)      // 3072 zssim blocks

#define C1f 1.0e-4f
#define C2f 9.0e-4f

struct Wts { float w[11]; };

// Scratch (no mallocs allowed): 5 xy-blurred channel planes + partials.
__device__ float g_scrA[5ull * NTOT];
__device__ float g_part[NPART];

// ---------------------------------------------------------------------------
// Pass 1: fused channel-gen + x-blur + y-blur, split into 4 y-segments.
// Block = (b, z, y-segment of 48 rows). 192 threads (one per x).
// Raw rows staged in ping-pong smem (x-halo zero, single sync per row);
// y window kept in a thread-private 5ch x 11 register ring.
// Every global address is clamped in-bounds; padding via select after load.
// ---------------------------------------------------------------------------
__global__ void __launch_bounds__(192) k_xyblur(const float* __restrict__ gt,
                                                const float* __restrict__ pr,
                                                Wts W) {
    __shared__ float sg[2][DIMX + 10];
    __shared__ float sp[2][DIMX + 10];
    const int x  = threadIdx.x;          // 0..191
    const int z  = blockIdx.x;           // 0..191
    const int ys = blockIdx.y * 48;      // 0,48,96,144
    const int b  = blockIdx.z;           // 0..3

    const size_t slice = (((size_t)b * DIMZ + z) * DIMY) * DIMX;

    if (x < 5) {
        sg[0][x] = 0.f; sg[1][x] = 0.f; sp[0][x] = 0.f; sp[1][x] = 0.f;
        sg[0][DIMX + 5 + x] = 0.f; sg[1][DIMX + 5 + x] = 0.f;
        sp[0][DIMX + 5 + x] = 0.f; sp[1][DIMX + 5 + x] = 0.f;
    }

    float win[5][11];
#pragma unroll
    for (int c = 0; c < 5; ++c)
#pragma unroll
        for (int s = 0; s < 11; ++s) win[c][s] = 0.f;

    // Prologue: u = 0..9 -> raw row yin = ys-5+u, x-blur into ring slot u.
#pragma unroll
    for (int u = 0; u < 10; ++u) {
        const int yin = ys - 5 + u;
        const int yc  = (yin >= 0) ? ((yin < DIMY) ? yin : (DIMY - 1)) : 0;
        float gv = gt[slice + (size_t)yc * DIMX + x];
        float pv = pr[slice + (size_t)yc * DIMX + x];
        if (yin < 0 || yin >= DIMY) { gv = 0.f; pv = 0.f; }
        const int p = u & 1;
        sg[p][x + 5] = gv;
        sp[p][x + 5] = pv;
        __syncthreads();
        float s0 = 0.f, s1 = 0.f, s2 = 0.f, s3 = 0.f, s4 = 0.f;
#pragma unroll
        for (int k = 0; k < 11; ++k) {
            const float wk = W.w[k];
            const float g2 = sg[p][x + k];
            const float p2 = sp[p][x + k];
            const float tg = wk * g2, tp = wk * p2;
            s0 += tg; s1 += tp; s2 += tg * g2; s3 += tp * p2; s4 += tg * p2;
        }
        win[0][u] = s0; win[1][u] = s1; win[2][u] = s2;
        win[3][u] = s3; win[4][u] = s4;
    }

    // Main: outputs j = 0..47 (y = ys+j); insert u = j+10 (yin = ys+j+5).
    for (int jb = 0; jb < 48; jb += 11) {
#pragma unroll
        for (int i = 0; i < 11; ++i) {
            const int j = jb + i;          // uniform across block
            if (j < 48) {
                const int yin = ys + j + 5;
                const int yc  = (yin < DIMY) ? yin : (DIMY - 1);
                float gv = gt[slice + (size_t)yc * DIMX + x];
                float pv = pr[slice + (size_t)yc * DIMX + x];
                if (yin >= DIMY) { gv = 0.f; pv = 0.f; }
                const int p = (j + 10) & 1;
                sg[p][x + 5] = gv;
                sp[p][x + 5] = pv;
                __syncthreads();

                // x-blur -> ring slot (i+10)%11 (static per i).
                const int slot = (i + 10) % 11;
                {
                    float s0 = 0.f, s1 = 0.f, s2 = 0.f, s3 = 0.f, s4 = 0.f;
#pragma unroll
                    for (int k = 0; k < 11; ++k) {
                        const float wk = W.w[k];
                        const float g2 = sg[p][x + k];
                        const float p2 = sp[p][x + k];
                        const float tg = wk * g2, tp = wk * p2;
                        s0 += tg; s1 += tp; s2 += tg * g2; s3 += tp * p2; s4 += tg * p2;
                    }
                    win[0][slot] = s0; win[1][slot] = s1; win[2][slot] = s2;
                    win[3][slot] = s3; win[4][slot] = s4;
                }

                // y-blur: tap t uses slot (i+t)%11 (static).
                float m0 = 0.f, m1 = 0.f, m2 = 0.f, m3 = 0.f, m4 = 0.f;
#pragma unroll
                for (int t = 0; t < 11; ++t) {
                    const int s = (i + t) % 11;
                    const float wk = W.w[t];
                    m0 += wk * win[0][s];
                    m1 += wk * win[1][s];
                    m2 += wk * win[2][s];
                    m3 += wk * win[3][s];
                    m4 += wk * win[4][s];
                }
                const size_t oidx = slice + (size_t)(ys + j) * DIMX + x;
                g_scrA[0ull * NTOT + oidx] = m0;
                g_scrA[1ull * NTOT + oidx] = m1;
                g_scrA[2ull * NTOT + oidx] = m2;
                g_scrA[3ull * NTOT + oidx] = m3;
                g_scrA[4ull * NTOT + oidx] = m4;
            }
        }
    }
}

// ---------------------------------------------------------------------------
// Pass 2: z-blur + SSIM + block-partial reduction (4 z-segments).
// ---------------------------------------------------------------------------
__global__ void __launch_bounds__(192) k_zssim(Wts W) {
    const int x = threadIdx.x;
    const int y = blockIdx.x;
    const int seg = blockIdx.y;          // 0..3
    const int b = blockIdx.z;
    const int zs = seg * 48;

    const size_t colbase = (((size_t)b * DIMZ) * DIMY + y) * DIMX + x;
    const size_t zstride = (size_t)DIMY * DIMX;

    float win[5][11];
#pragma unroll
    for (int c = 0; c < 5; ++c)
#pragma unroll
        for (int s = 0; s < 11; ++s) win[c][s] = 0.f;

#pragma unroll
    for (int u = 0; u < 10; ++u) {
        const int zin = zs - 5 + u;
        const int zc = (zin >= 0) ? zin : 0;
        const size_t off = colbase + (size_t)zc * zstride;
#pragma unroll
        for (int c = 0; c < 5; ++c) {
            const float v = g_scrA[(size_t)c * NTOT + off];
            win[c][u] = (zin >= 0) ? v : 0.f;
        }
    }

    float acc = 0.f;
    for (int jb = 0; jb < 48; jb += 11) {
#pragma unroll
        for (int i = 0; i < 11; ++i) {
            const int j = jb + i;
            if (j < 48) {
                const int slot = (i + 10) % 11;
                const int zin = zs + j + 5;
                const int zc = (zin < DIMZ) ? zin : (DIMZ - 1);
                const size_t off = colbase + (size_t)zc * zstride;
#pragma unroll
                for (int c = 0; c < 5; ++c) {
                    const float v = g_scrA[(size_t)c * NTOT + off];
                    win[c][slot] = (zin < DIMZ) ? v : 0.f;
                }

                float m0 = 0.f, m1 = 0.f, m2 = 0.f, m3 = 0.f, m4 = 0.f;
#pragma unroll
                for (int t = 0; t < 11; ++t) {
                    const int s = (i + t) % 11;   // static
                    const float wk = W.w[t];
                    m0 += wk * win[0][s];
                    m1 += wk * win[1][s];
                    m2 += wk * win[2][s];
                    m3 += wk * win[3][s];
                    m4 += wk * win[4][s];
                }
                const float mux = m0, muy = m1;
                const float mux2 = mux * mux;
                const float muy2 = muy * muy;
                const float muxy = mux * muy;
                const float sx = m2 - mux2;
                const float sy = m3 - muy2;
                const float sxy = m4 - muxy;
                const float num = (2.f * muxy + C1f) * (2.f * sxy + C2f);
                const float den = (mux2 + muy2 + C1f) * (sx + sy + C2f);
                acc += 1.f - __fdividef(num, den);
            }
        }
    }

    __shared__ float red[6];
    float v = acc;
#pragma unroll
    for (int o = 16; o > 0; o >>= 1)
        v += __shfl_down_sync(0xffffffffu, v, o);
    const int wid = threadIdx.x >> 5;
    if ((threadIdx.x & 31) == 0) red[wid] = v;
    __syncthreads();
    if (threadIdx.x == 0) {
        float t = 0.f;
#pragma unroll
        for (int w = 0; w < 6; ++w) t += red[w];
        const int bn = blockIdx.x + DIMY * (blockIdx.y + 4 * blockIdx.z);
        g_part[bn] = t;
    }
}

// ---------------------------------------------------------------------------
// Final: sum 3072 partials (double), write mean(1-ssim).
// ---------------------------------------------------------------------------
__global__ void __launch_bounds__(256) k_final(float* __restrict__ out) {
    __shared__ double red[8];
    double s = 0.0;
    for (int i = threadIdx.x; i < NPART; i += 256)
        s += (double)g_part[i];
#pragma unroll
    for (int o = 16; o > 0; o >>= 1)
        s += __shfl_down_sync(0xffffffffu, s, o);
    if ((threadIdx.x & 31) == 0) red[threadIdx.x >> 5] = s;
    __syncthreads();
    if (threadIdx.x == 0) {
        double t = 0.0;
#pragma unroll
        for (int w = 0; w < 8; ++w) t += red[w];
        out[0] = (float)(t * (1.0 / (double)NTOT));
    }
}

// ---------------------------------------------------------------------------
extern "C" void kernel_launch(void* const* d_in, const int* in_sizes, int n_in,
                              void* d_out, int out_size) {
    const float* gt = (const float*)d_in[0];
    const float* pr = (const float*)d_in[1];
    float* out = (float*)d_out;

    Wts W;
    {
        double g[11], sum = 0.0;
        for (int i = 0; i < 11; ++i) {
            const double xx = (double)(i - 5);
            g[i] = exp(-(xx * xx) / (2.0 * 1.5 * 1.5));
            sum += g[i];
        }
        for (int i = 0; i < 11; ++i) W.w[i] = (float)(g[i] / sum);
    }

    k_xyblur<<<dim3(DIMZ, 4, BDIM), 192>>>(gt, pr, W);
    k_zssim<<<dim3(DIMY, 4, BDIM), 192>>>(W);
    k_final<<<1, 256>>>(out);
}

// round 5
// speedup vs baseline: 1.7684x; 1.1170x over previous
#include <cuda_runtime.h>

#define BDIM 4
#define DIMZ 192
#define DIMY 192
#define DIMX 192
#define NTOT (BDIM*DIMZ*DIMY*DIMX)   // 28,311,552
#define ZSEG 6
#define ZLEN 32
#define NPART (DIMY * ZSEG * BDIM)   // 4608

#define C1f 1.0e-4f
#define C2f 9.0e-4f

// Gaussian weights (sigma=1.5, k=11), computed in float64 and rounded.
// Compile-time constants -> FFMA-imm form (rt_SMSP=1) in SASS.
__device__ constexpr float GW[11] = {
    0.00102838f, 0.00759876f, 0.03600077f, 0.10936069f, 0.21300554f,
    0.26601172f,
    0.21300554f, 0.10936069f, 0.03600077f, 0.00759876f, 0.00102838f
};

// Scratch (no mallocs allowed): 5 xy-blurred channel planes + partials.
__device__ float g_scrA[5ull * NTOT];
__device__ float g_part[NPART];

// Load one raw row segment (42 values via <=2 loads/lane) with every address
// clamped in-bounds; zero-padding applied by select AFTER the load.
__device__ __forceinline__ void load_row(const float* __restrict__ gt,
                                         const float* __restrict__ pr,
                                         size_t slice, int yin,
                                         int x1, int x2, bool do2,
                                         float& g1, float& p1,
                                         float& g2, float& p2) {
    const bool yok = (yin >= 0) && (yin < DIMY);
    const int yc = yin < 0 ? 0 : (yin >= DIMY ? DIMY - 1 : yin);
    const size_t rb = slice + (size_t)yc * DIMX;
    const int xc1 = x1 < 0 ? 0 : x1;          // x1 <= 186 always
    const float a = gt[rb + xc1];
    const float c = pr[rb + xc1];
    const bool ok1 = yok && (x1 >= 0);
    g1 = ok1 ? a : 0.f;
    p1 = ok1 ? c : 0.f;
    g2 = 0.f; p2 = 0.f;
    if (do2) {
        const int xc2 = (x2 < DIMX) ? x2 : (DIMX - 1);
        const float d = gt[rb + xc2];
        const float e = pr[rb + xc2];
        const bool ok2 = yok && (x2 < DIMX);
        g2 = ok2 ? d : 0.f;
        p2 = ok2 ? e : 0.f;
    }
}

// ---------------------------------------------------------------------------
// Pass 1: fused channel-gen + x-blur + y-blur. Block = (b, z, y-seg of 48).
// Each WARP independently owns a 32-wide x strip: raw rows staged in a
// per-warp ping-pong smem strip (42 wide, halo loads), one __syncwarp per
// row, depth-1 register prefetch of the next row. No block barriers.
// y window: thread-private 5ch x 11 register ring (static indices).
// ---------------------------------------------------------------------------
__global__ void __launch_bounds__(192, 4)
k_xyblur(const float* __restrict__ gt, const float* __restrict__ pr) {
    __shared__ float sb[6][2][2][44];   // [warp][buf][g/p][42 used]
    const int tid  = threadIdx.x;
    const int lane = tid & 31;
    const int wrp  = tid >> 5;
    const int xbase = wrp * 32;
    const int x  = xbase + lane;
    const int x1 = xbase - 5 + lane;          // first staged position
    const int x2 = xbase + 27 + lane;         // second (lanes 0..9)
    const bool do2 = (lane < 10);
    const int z  = blockIdx.x;
    const int ys = blockIdx.y * 48;
    const int b  = blockIdx.z;
    const size_t slice = (((size_t)b * DIMZ + z) * DIMY) * DIMX;

    float win[5][11];
#pragma unroll
    for (int c = 0; c < 5; ++c)
#pragma unroll
        for (int s = 0; s < 11; ++s) win[c][s] = 0.f;

    float g1, p1, g2, p2;
    load_row(gt, pr, slice, ys - 5, x1, x2, do2, g1, p1, g2, p2);

    // Prologue: rows yin = ys-5+u for u = 0..9 -> ring slot u.
#pragma unroll
    for (int u = 0; u < 10; ++u) {
        const int buf = u & 1;
        sb[wrp][buf][0][lane] = g1;
        sb[wrp][buf][1][lane] = p1;
        if (do2) {
            sb[wrp][buf][0][32 + lane] = g2;
            sb[wrp][buf][1][32 + lane] = p2;
        }
        __syncwarp();
        load_row(gt, pr, slice, ys - 4 + u, x1, x2, do2, g1, p1, g2, p2);

        float s0 = 0.f, s1 = 0.f, s2 = 0.f, s3 = 0.f, s4 = 0.f;
#pragma unroll
        for (int k = 0; k < 11; ++k) {
            const float gv = sb[wrp][buf][0][lane + k];
            const float pv = sb[wrp][buf][1][lane + k];
            s0 += GW[k] * gv;
            s1 += GW[k] * pv;
            const float tg = GW[k] * gv;
            s2 += tg * gv;
            s4 += tg * pv;
            const float tp = GW[k] * pv;
            s3 += tp * pv;
        }
        win[0][u] = s0; win[1][u] = s1; win[2][u] = s2;
        win[3][u] = s3; win[4][u] = s4;
    }

    // Main: outputs j = 0..47 (y = ys+j); insert row yin = ys+j+5.
    for (int jb = 0; jb < 48; jb += 11) {
#pragma unroll
        for (int i = 0; i < 11; ++i) {
            const int j = jb + i;
            if (j < 48) {
                const int buf = j & 1;   // continues prologue alternation
                sb[wrp][buf][0][lane] = g1;
                sb[wrp][buf][1][lane] = p1;
                if (do2) {
                    sb[wrp][buf][0][32 + lane] = g2;
                    sb[wrp][buf][1][32 + lane] = p2;
                }
                __syncwarp();
                // Prefetch next row (yin = ys+j+6), clamped + zero-selected.
                load_row(gt, pr, slice, ys + j + 6, x1, x2, do2, g1, p1, g2, p2);

                // x-blur -> ring slot (i+10)%11 (static per i).
                const int slot = (i + 10) % 11;
                {
                    float s0 = 0.f, s1 = 0.f, s2 = 0.f, s3 = 0.f, s4 = 0.f;
#pragma unroll
                    for (int k = 0; k < 11; ++k) {
                        const float gv = sb[wrp][buf][0][lane + k];
                        const float pv = sb[wrp][buf][1][lane + k];
                        s0 += GW[k] * gv;
                        s1 += GW[k] * pv;
                        const float tg = GW[k] * gv;
                        s2 += tg * gv;
                        s4 += tg * pv;
                        const float tp = GW[k] * pv;
                        s3 += tp * pv;
                    }
                    win[0][slot] = s0; win[1][slot] = s1; win[2][slot] = s2;
                    win[3][slot] = s3; win[4][slot] = s4;
                }

                // y-blur: tap t uses slot (i+t)%11 (static).
                float m0 = 0.f, m1 = 0.f, m2 = 0.f, m3 = 0.f, m4 = 0.f;
#pragma unroll
                for (int t = 0; t < 11; ++t) {
                    const int s = (i + t) % 11;
                    m0 += GW[t] * win[0][s];
                    m1 += GW[t] * win[1][s];
                    m2 += GW[t] * win[2][s];
                    m3 += GW[t] * win[3][s];
                    m4 += GW[t] * win[4][s];
                }
                const size_t oidx = slice + (size_t)(ys + j) * DIMX + x;
                g_scrA[0ull * NTOT + oidx] = m0;
                g_scrA[1ull * NTOT + oidx] = m1;
                g_scrA[2ull * NTOT + oidx] = m2;
                g_scrA[3ull * NTOT + oidx] = m3;
                g_scrA[4ull * NTOT + oidx] = m4;
            }
        }
    }
}

// ---------------------------------------------------------------------------
// Pass 2: z-blur + SSIM + block-partial reduction. 6 z-segments of 32,
// clamped depth-1 prefetch of the 5 channel loads.
// ---------------------------------------------------------------------------
__global__ void __launch_bounds__(192, 4) k_zssim() {
    const int x = threadIdx.x;
    const int y = blockIdx.x;
    const int zs = blockIdx.y * ZLEN;     // 0,32,...,160
    const int b = blockIdx.z;

    const size_t colbase = (((size_t)b * DIMZ) * DIMY + y) * DIMX + x;
    const size_t zstride = (size_t)DIMY * DIMX;

    float win[5][11];
#pragma unroll
    for (int c = 0; c < 5; ++c)
#pragma unroll
        for (int s = 0; s < 11; ++s) win[c][s] = 0.f;

    // Prologue: u = 0..9 -> zin = zs-5+u (clamp low; high end <= 164 ok).
#pragma unroll
    for (int u = 0; u < 10; ++u) {
        const int zin = zs - 5 + u;
        const int zc = (zin >= 0) ? zin : 0;
        const size_t off = colbase + (size_t)zc * zstride;
#pragma unroll
        for (int c = 0; c < 5; ++c) {
            const float v = g_scrA[(size_t)c * NTOT + off];
            win[c][u] = (zin >= 0) ? v : 0.f;
        }
    }

    // Prefetch u = 10 (zin = zs+5 <= 165, always valid).
    float pf[5];
    {
        const size_t off = colbase + (size_t)(zs + 5) * zstride;
#pragma unroll
        for (int c = 0; c < 5; ++c)
            pf[c] = g_scrA[(size_t)c * NTOT + off];
    }

    float acc = 0.f;
    for (int jb = 0; jb < ZLEN; jb += 11) {
#pragma unroll
        for (int i = 0; i < 11; ++i) {
            const int j = jb + i;
            if (j < ZLEN) {
                // Insert prefetched u = j+10 at slot (i+10)%11 (static).
                const int slot = (i + 10) % 11;
#pragma unroll
                for (int c = 0; c < 5; ++c) win[c][slot] = pf[c];

                // Prefetch u = j+11 (zin = zs+j+6), clamped + selected.
                {
                    const int zin = zs + j + 6;
                    const int zc = (zin < DIMZ) ? zin : (DIMZ - 1);
                    const size_t off = colbase + (size_t)zc * zstride;
#pragma unroll
                    for (int c = 0; c < 5; ++c) {
                        const float v = g_scrA[(size_t)c * NTOT + off];
                        pf[c] = (zin < DIMZ) ? v : 0.f;
                    }
                }

                float m0 = 0.f, m1 = 0.f, m2 = 0.f, m3 = 0.f, m4 = 0.f;
#pragma unroll
                for (int t = 0; t < 11; ++t) {
                    const int s = (i + t) % 11;   // static
                    m0 += GW[t] * win[0][s];
                    m1 += GW[t] * win[1][s];
                    m2 += GW[t] * win[2][s];
                    m3 += GW[t] * win[3][s];
                    m4 += GW[t] * win[4][s];
                }
                const float mux = m0, muy = m1;
                const float mux2 = mux * mux;
                const float muy2 = muy * muy;
                const float muxy = mux * muy;
                const float sx = m2 - mux2;
                const float sy = m3 - muy2;
                const float sxy = m4 - muxy;
                const float num = (2.f * muxy + C1f) * (2.f * sxy + C2f);
                const float den = (mux2 + muy2 + C1f) * (sx + sy + C2f);
                acc += 1.f - __fdividef(num, den);
            }
        }
    }

    __shared__ float red[6];
    float v = acc;
#pragma unroll
    for (int o = 16; o > 0; o >>= 1)
        v += __shfl_down_sync(0xffffffffu, v, o);
    const int wid = threadIdx.x >> 5;
    if ((threadIdx.x & 31) == 0) red[wid] = v;
    __syncthreads();
    if (threadIdx.x == 0) {
        float t = 0.f;
#pragma unroll
        for (int w = 0; w < 6; ++w) t += red[w];
        const int bn = blockIdx.x + DIMY * (blockIdx.y + ZSEG * blockIdx.z);
        g_part[bn] = t;
    }
}

// ---------------------------------------------------------------------------
// Final: sum partials (double), write mean(1-ssim).
// ---------------------------------------------------------------------------
__global__ void __launch_bounds__(256) k_final(float* __restrict__ out) {
    __shared__ double red[8];
    double s = 0.0;
    for (int i = threadIdx.x; i < NPART; i += 256)
        s += (double)g_part[i];
#pragma unroll
    for (int o = 16; o > 0; o >>= 1)
        s += __shfl_down_sync(0xffffffffu, s, o);
    if ((threadIdx.x & 31) == 0) red[threadIdx.x >> 5] = s;
    __syncthreads();
    if (threadIdx.x == 0) {
        double t = 0.0;
#pragma unroll
        for (int w = 0; w < 8; ++w) t += red[w];
        out[0] = (float)(t * (1.0 / (double)NTOT));
    }
}

// ---------------------------------------------------------------------------
extern "C" void kernel_launch(void* const* d_in, const int* in_sizes, int n_in,
                              void* d_out, int out_size) {
    const float* gt = (const float*)d_in[0];
    const float* pr = (const float*)d_in[1];
    float* out = (float*)d_out;

    k_xyblur<<<dim3(DIMZ, 4, BDIM), 192>>>(gt, pr);
    k_zssim<<<dim3(DIMY, ZSEG, BDIM), 192>>>();
    k_final<<<1, 256>>>(out);
}

// round 6
// speedup vs baseline: 1.9071x; 1.0784x over previous
#include <cuda_runtime.h>
#include <cuda_fp16.h>

#define BDIM 4
#define DIMZ 192
#define DIMY 192
#define DIMX 192
#define NTOT (BDIM*DIMZ*DIMY*DIMX)   // 28,311,552
#define ZSEG 6
#define ZLEN 32
#define NPART (DIMY * ZSEG * BDIM)   // 4608

#define C1f 1.0e-4f
#define C2f 9.0e-4f

typedef unsigned long long ull;

// Gaussian weights (sigma=1.5, k=11): compile-time immediates.
__device__ constexpr float GW[11] = {
    0.00102838f, 0.00759876f, 0.03600077f, 0.10936069f, 0.21300554f,
    0.26601172f,
    0.21300554f, 0.10936069f, 0.03600077f, 0.00759876f, 0.00102838f
};

// Intermediate storage: fp16 with offsets (values ~ +-0.06 interior).
// ch0/1 = xy-blur(g), xy-blur(p) - 0.5 ; ch2/3 = xy-blur(g^2),(p^2) - 1/3 ;
// ch4 = xy-blur(g*p) - 1/4.
__device__ __half2 g_h01[NTOT];
__device__ __half2 g_h23[NTOT];
__device__ __half  g_h4 [NTOT];
__device__ float   g_part[NPART];

// ---- packed f32x2 helpers -------------------------------------------------
__device__ __forceinline__ ull pk2(float x, float y) {
    ull r; asm("mov.b64 %0, {%1,%2};" : "=l"(r) : "f"(x), "f"(y)); return r;
}
__device__ __forceinline__ void upk2(ull v, float& x, float& y) {
    asm("mov.b64 {%0,%1}, %2;" : "=f"(x), "=f"(y) : "l"(v));
}
__device__ __forceinline__ ull mul2_(ull a, ull b) {
    ull d; asm("mul.rn.f32x2 %0, %1, %2;" : "=l"(d) : "l"(a), "l"(b)); return d;
}
__device__ __forceinline__ ull add2_(ull a, ull b) {
    ull d; asm("add.rn.f32x2 %0, %1, %2;" : "=l"(d) : "l"(a), "l"(b)); return d;
}
__device__ __forceinline__ ull fma2_(ull a, ull b, ull c) {
    ull d; asm("fma.rn.f32x2 %0, %1, %2, %3;" : "=l"(d) : "l"(a), "l"(b), "l"(c));
    return d;
}

// Clamped raw-row loader (addresses always in-bounds; zero-select after).
__device__ __forceinline__ void load_row(const float* __restrict__ gt,
                                         const float* __restrict__ pr,
                                         size_t slice, int yin,
                                         int x1, int x2, bool do2,
                                         float& g1, float& p1,
                                         float& g2, float& p2) {
    const bool yok = (yin >= 0) && (yin < DIMY);
    const int yc = yin < 0 ? 0 : (yin >= DIMY ? DIMY - 1 : yin);
    const size_t rb = slice + (size_t)yc * DIMX;
    const int xc1 = x1 < 0 ? 0 : x1;
    const float a = gt[rb + xc1];
    const float c = pr[rb + xc1];
    const bool ok1 = yok && (x1 >= 0);
    g1 = ok1 ? a : 0.f;
    p1 = ok1 ? c : 0.f;
    g2 = 0.f; p2 = 0.f;
    if (do2) {
        const int xc2 = (x2 < DIMX) ? x2 : (DIMX - 1);
        const float d = gt[rb + xc2];
        const float e = pr[rb + xc2];
        const bool ok2 = yok && (x2 < DIMX);
        g2 = ok2 ? d : 0.f;
        p2 = ok2 ? e : 0.f;
    }
}

// ---------------------------------------------------------------------------
// Pass 1: fused channel-gen + x-blur + y-blur (per-warp strips, packed math).
// ---------------------------------------------------------------------------
__global__ void __launch_bounds__(192)
k_xyblur(const float* __restrict__ gt, const float* __restrict__ pr) {
    __shared__ ull   sbv[6][2][44];   // packed (g,p) raw rows per warp
    __shared__ float sgp[6][2][44];   // g*p raw rows per warp
    const int tid  = threadIdx.x;
    const int lane = tid & 31;
    const int wrp  = tid >> 5;
    const int xbase = wrp * 32;
    const int x  = xbase + lane;
    const int x1 = xbase - 5 + lane;
    const int x2 = xbase + 27 + lane;
    const bool do2 = (lane < 10);
    const int z  = blockIdx.x;
    const int ys = blockIdx.y * 48;
    const int b  = blockIdx.z;
    const size_t slice = (((size_t)b * DIMZ + z) * DIMY) * DIMX;

    // Hoisted packed weights (6 distinct, symmetric).
    const ull vw0 = pk2(GW[0], GW[0]);
    const ull vw1 = pk2(GW[1], GW[1]);
    const ull vw2 = pk2(GW[2], GW[2]);
    const ull vw3 = pk2(GW[3], GW[3]);
    const ull vw4 = pk2(GW[4], GW[4]);
    const ull vw5 = pk2(GW[5], GW[5]);
    const ull vw[11] = {vw0,vw1,vw2,vw3,vw4,vw5,vw4,vw3,vw2,vw1,vw0};

    const ull zero2 = pk2(0.f, 0.f);
    ull win01[11], win23[11];
    float win4[11];
#pragma unroll
    for (int s = 0; s < 11; ++s) { win01[s] = zero2; win23[s] = zero2; win4[s] = 0.f; }

    float g1, p1, g2, p2;
    load_row(gt, pr, slice, ys - 5, x1, x2, do2, g1, p1, g2, p2);

    // Prologue: rows yin = ys-5+u for u = 0..9 -> ring slot u.
#pragma unroll
    for (int u = 0; u < 10; ++u) {
        const int buf = u & 1;
        sbv[wrp][buf][lane] = pk2(g1, p1);
        sgp[wrp][buf][lane] = g1 * p1;
        if (do2) {
            sbv[wrp][buf][32 + lane] = pk2(g2, p2);
            sgp[wrp][buf][32 + lane] = g2 * p2;
        }
        __syncwarp();
        load_row(gt, pr, slice, ys - 4 + u, x1, x2, do2, g1, p1, g2, p2);

        ull s01 = zero2, s23 = zero2;
        float s4 = 0.f;
#pragma unroll
        for (int k = 0; k < 11; ++k) {
            const ull v = sbv[wrp][buf][lane + k];
            const ull t = mul2_(vw[k], v);
            s01 = add2_(s01, t);
            s23 = fma2_(t, v, s23);
            s4 = fmaf(GW[k], sgp[wrp][buf][lane + k], s4);
        }
        win01[u] = s01; win23[u] = s23; win4[u] = s4;
    }

    // Main: outputs j = 0..47 (y = ys+j); insert row yin = ys+j+5.
    for (int jb = 0; jb < 48; jb += 11) {
#pragma unroll
        for (int i = 0; i < 11; ++i) {
            const int j = jb + i;
            if (j < 48) {
                const int buf = j & 1;   // continues prologue alternation
                sbv[wrp][buf][lane] = pk2(g1, p1);
                sgp[wrp][buf][lane] = g1 * p1;
                if (do2) {
                    sbv[wrp][buf][32 + lane] = pk2(g2, p2);
                    sgp[wrp][buf][32 + lane] = g2 * p2;
                }
                __syncwarp();
                load_row(gt, pr, slice, ys + j + 6, x1, x2, do2, g1, p1, g2, p2);

                // x-blur -> ring slot (i+10)%11 (static per i).
                const int slot = (i + 10) % 11;
                {
                    ull s01 = zero2, s23 = zero2;
                    float s4 = 0.f;
#pragma unroll
                    for (int k = 0; k < 11; ++k) {
                        const ull v = sbv[wrp][buf][lane + k];
                        const ull t = mul2_(vw[k], v);
                        s01 = add2_(s01, t);
                        s23 = fma2_(t, v, s23);
                        s4 = fmaf(GW[k], sgp[wrp][buf][lane + k], s4);
                    }
                    win01[slot] = s01; win23[slot] = s23; win4[slot] = s4;
                }

                // y-blur: tap t uses slot (i+t)%11 (static).
                ull m01 = zero2, m23 = zero2;
                float m4 = 0.f;
#pragma unroll
                for (int t = 0; t < 11; ++t) {
                    const int s = (i + t) % 11;
                    m01 = fma2_(vw[t], win01[s], m01);
                    m23 = fma2_(vw[t], win23[s], m23);
                    m4 = fmaf(GW[t], win4[s], m4);
                }
                float f0, f1, f2, f3;
                upk2(m01, f0, f1);
                upk2(m23, f2, f3);
                const float OFF23 = 1.0f / 3.0f;
                const size_t oidx = slice + (size_t)(ys + j) * DIMX + x;
                g_h01[oidx] = __floats2half2_rn(f0 - 0.5f, f1 - 0.5f);
                g_h23[oidx] = __floats2half2_rn(f2 - OFF23, f3 - OFF23);
                g_h4 [oidx] = __float2half_rn(m4 - 0.25f);
            }
        }
    }
}

// ---------------------------------------------------------------------------
// Pass 2: z-blur + SSIM + block-partial reduction (6 z-segments of 32).
// Out-of-range z taps filled with -OFF so the offset reconstruction equals
// the zero-padded blur exactly. Depth-1 prefetch, clamped addresses.
// ---------------------------------------------------------------------------
__global__ void __launch_bounds__(192) k_zssim() {
    const int x = threadIdx.x;
    const int y = blockIdx.x;
    const int zs = blockIdx.y * ZLEN;
    const int b = blockIdx.z;

    const size_t colbase = (((size_t)b * DIMZ) * DIMY + y) * DIMX + x;
    const size_t zstride = (size_t)DIMY * DIMX;
    const float OFF23 = 1.0f / 3.0f;

    const ull vw0 = pk2(GW[0], GW[0]);
    const ull vw1 = pk2(GW[1], GW[1]);
    const ull vw2 = pk2(GW[2], GW[2]);
    const ull vw3 = pk2(GW[3], GW[3]);
    const ull vw4 = pk2(GW[4], GW[4]);
    const ull vw5 = pk2(GW[5], GW[5]);
    const ull vw[11] = {vw0,vw1,vw2,vw3,vw4,vw5,vw4,vw3,vw2,vw1,vw0};

    const ull n01 = pk2(-0.5f, -0.5f);
    const ull n23 = pk2(-OFF23, -OFF23);
    const float n4 = -0.25f;
    const ull zero2 = pk2(0.f, 0.f);

    ull win01[11], win23[11];
    float win4[11];

    // Prologue: u = 0..9 -> zin = zs-5+u (clamped; -OFF fill when invalid).
#pragma unroll
    for (int u = 0; u < 10; ++u) {
        const int zin = zs - 5 + u;
        const int zc = (zin >= 0) ? zin : 0;
        const size_t off = colbase + (size_t)zc * zstride;
        const float2 a = __half22float2(g_h01[off]);
        const float2 c = __half22float2(g_h23[off]);
        const float  e = __half2float(g_h4[off]);
        const bool ok = (zin >= 0);
        win01[u] = ok ? pk2(a.x, a.y) : n01;
        win23[u] = ok ? pk2(c.x, c.y) : n23;
        win4[u]  = ok ? e : n4;
    }

    // Prefetch u = 10 (zin = zs+5, always valid: <= 165).
    ull pf01, pf23; float pf4;
    {
        const size_t off = colbase + (size_t)(zs + 5) * zstride;
        const float2 a = __half22float2(g_h01[off]);
        const float2 c = __half22float2(g_h23[off]);
        pf01 = pk2(a.x, a.y);
        pf23 = pk2(c.x, c.y);
        pf4  = __half2float(g_h4[off]);
    }

    float acc = 0.f;
    for (int jb = 0; jb < ZLEN; jb += 11) {
#pragma unroll
        for (int i = 0; i < 11; ++i) {
            const int j = jb + i;
            if (j < ZLEN) {
                const int slot = (i + 10) % 11;
                win01[slot] = pf01; win23[slot] = pf23; win4[slot] = pf4;

                // Prefetch u = j+11 (zin = zs+j+6), clamped + -OFF select.
                {
                    const int zin = zs + j + 6;
                    const int zc = (zin < DIMZ) ? zin : (DIMZ - 1);
                    const size_t off = colbase + (size_t)zc * zstride;
                    const float2 a = __half22float2(g_h01[off]);
                    const float2 c = __half22float2(g_h23[off]);
                    const float  e = __half2float(g_h4[off]);
                    const bool ok = (zin < DIMZ);
                    pf01 = ok ? pk2(a.x, a.y) : n01;
                    pf23 = ok ? pk2(c.x, c.y) : n23;
                    pf4  = ok ? e : n4;
                }

                ull m01 = zero2, m23 = zero2;
                float m4 = 0.f;
#pragma unroll
                for (int t = 0; t < 11; ++t) {
                    const int s = (i + t) % 11;   // static
                    m01 = fma2_(vw[t], win01[s], m01);
                    m23 = fma2_(vw[t], win23[s], m23);
                    m4 = fmaf(GW[t], win4[s], m4);
                }
                float mx, my, e2g, e2p;
                upk2(m01, mx, my);
                upk2(m23, e2g, e2p);
                const float mux = mx + 0.5f;
                const float muy = my + 0.5f;
                const float eg2 = e2g + OFF23;
                const float ep2 = e2p + OFF23;
                const float egp = m4 + 0.25f;
                const float mux2 = mux * mux;
                const float muy2 = muy * muy;
                const float muxy = mux * muy;
                const float sx = eg2 - mux2;
                const float sy = ep2 - muy2;
                const float sxy = egp - muxy;
                const float num = (2.f * muxy + C1f) * (2.f * sxy + C2f);
                const float den = (mux2 + muy2 + C1f) * (sx + sy + C2f);
                acc += 1.f - __fdividef(num, den);
            }
        }
    }

    __shared__ float red[6];
    float v = acc;
#pragma unroll
    for (int o = 16; o > 0; o >>= 1)
        v += __shfl_down_sync(0xffffffffu, v, o);
    const int wid = threadIdx.x >> 5;
    if ((threadIdx.x & 31) == 0) red[wid] = v;
    __syncthreads();
    if (threadIdx.x == 0) {
        float t = 0.f;
#pragma unroll
        for (int w = 0; w < 6; ++w) t += red[w];
        const int bn = blockIdx.x + DIMY * (blockIdx.y + ZSEG * blockIdx.z);
        g_part[bn] = t;
    }
}

// ---------------------------------------------------------------------------
__global__ void __launch_bounds__(256) k_final(float* __restrict__ out) {
    __shared__ double red[8];
    double s = 0.0;
    for (int i = threadIdx.x; i < NPART; i += 256)
        s += (double)g_part[i];
#pragma unroll
    for (int o = 16; o > 0; o >>= 1)
        s += __shfl_down_sync(0xffffffffu, s, o);
    if ((threadIdx.x & 31) == 0) red[threadIdx.x >> 5] = s;
    __syncthreads();
    if (threadIdx.x == 0) {
        double t = 0.0;
#pragma unroll
        for (int w = 0; w < 8; ++w) t += red[w];
        out[0] = (float)(t * (1.0 / (double)NTOT));
    }
}

// ---------------------------------------------------------------------------
extern "C" void kernel_launch(void* const* d_in, const int* in_sizes, int n_in,
                              void* d_out, int out_size) {
    const float* gt = (const float*)d_in[0];
    const float* pr = (const float*)d_in[1];
    float* out = (float*)d_out;

    k_xyblur<<<dim3(DIMZ, 4, BDIM), 192>>>(gt, pr);
    k_zssim<<<dim3(DIMY, ZSEG, BDIM), 192>>>();
    k_final<<<1, 256>>>(out);
}